// round 1
// baseline (speedup 1.0000x reference)
#include <cuda_runtime.h>

// GraphAttention_14740327760460
//
// Dead-code analysis of the reference:
//   Wh2 = h @ W_out has shape [N, 1]; the final op is
//   log_softmax(out, axis=1) on a [N, 1] tensor, i.e. over a singleton
//   axis: x - logsumexp(x) == 0 exactly for all finite x. All rows of the
//   masked softmaxes are valid (adj includes self-loops), so every
//   intermediate is finite and the reference output is identically 0.0f.
//
// Hence the fastest correct kernel writes zeros to d_out. The harness
// poisons d_out to 0xAA before timing, so the write is mandatory.

__global__ void GraphAttention_14740327760460_zero(float* __restrict__ out, int n) {
    int i = blockIdx.x * blockDim.x + threadIdx.x;
    if (i < n) out[i] = 0.0f;
}

extern "C" void kernel_launch(void* const* d_in, const int* in_sizes, int n_in,
                              void* d_out, int out_size) {
    (void)d_in; (void)in_sizes; (void)n_in;
    float* out = (float*)d_out;
    int threads = 256;
    int blocks = (out_size + threads - 1) / threads;
    GraphAttention_14740327760460_zero<<<blocks, threads>>>(out, out_size);
}